// round 17
// baseline (speedup 1.0000x reference)
#include <cuda_runtime.h>
#include <cuda_fp16.h>
#include <cstdint>

// ---------------- problem dims ----------------
#define DM     2048
#define BATCHN 4
#define SEQ    2048
#define MTOT   (BATCHN*SEQ)   // 8192
#define NQKV   (3*DM)         // 6144

// ---------------- GEMM tiling ----------------
// fp16 operands, fp32 accum, mma.m16n8k16. Launch-per-tile (persistence tested
// worse). CTA tile 128x128x64, 128 threads (2x2 warps of 64x64). 3-stage
// cp.async pipeline, 96KB smem -> 2 CTAs/SM; 128 thr -> 255-reg budget, which
// admits REGISTER DOUBLE-BUFFERED fragments: LDSM of ks+1 issues before the
// 32 MMAs of ks, hiding the ~30cyc LDSM latency that stalls the lockstep warps.
#define BM 128
#define BN 128
#define BK 64
#define STAGES 3
#define NTHREADS 128
#define STG_BYTES (BM*BK*2)                   // 16384 B per matrix stage
#define SMEM_DYN (STAGES * 2 * STG_BYTES)     // 96 KB
#define NK 32                                 // K = 2048 = 32 x BK

// ---------------- scratch (device globals; no allocs allowed) ----------------
__device__ __half g_xh    [(size_t)MTOT * DM];
__device__ __half g_wqkvT [(size_t)NQKV * DM];
__device__ __half g_wfcT  [(size_t)DM * DM];
__device__ float  g_biasr [NQKV];
__device__ __half g_qkv   [(size_t)MTOT * NQKV];
__device__ __half g_scores[(size_t)BATCHN * SEQ * SEQ];
__device__ __half g_attn  [(size_t)BATCHN * SEQ * SEQ];

// ---------------- helpers ----------------
__device__ __forceinline__ uint32_t smem_u32(const void* p) {
    uint32_t a;
    asm("{ .reg .u64 t; cvta.to.shared.u64 t, %1; cvt.u32.u64 %0, t; }" : "=r"(a) : "l"(p));
    return a;
}
__device__ __forceinline__ void cp16(uint32_t saddr, const void* gaddr) {
    asm volatile("cp.async.cg.shared.global [%0], [%1], 16;\n" :: "r"(saddr), "l"(gaddr));
}
__device__ __forceinline__ void mma_f16_16816(float* d, const uint32_t* a, const uint32_t* b) {
    asm volatile(
        "mma.sync.aligned.m16n8k16.row.col.f32.f16.f16.f32 "
        "{%0,%1,%2,%3}, {%4,%5,%6,%7}, {%8,%9}, {%0,%1,%2,%3};\n"
        : "+f"(d[0]), "+f"(d[1]), "+f"(d[2]), "+f"(d[3])
        : "r"(a[0]), "r"(a[1]), "r"(a[2]), "r"(a[3]), "r"(b[0]), "r"(b[1]));
}
__device__ __forceinline__ void ldsm_x4(uint32_t* r, uint32_t addr) {
    asm volatile("ldmatrix.sync.aligned.m8n8.x4.shared.b16 {%0,%1,%2,%3}, [%4];"
                 : "=r"(r[0]), "=r"(r[1]), "=r"(r[2]), "=r"(r[3]) : "r"(addr));
}

// ---------------- fused prep kernel ----------------
#define NB_X  (MTOT*DM/2048)        // 8192
#define NB_TQ ((NQKV/32)*(DM/32))   // 12288
#define NB_TF ((DM/32)*(DM/32))     // 4096
#define NB_BP (NQKV/256)            // 24
#define NB_PREP (NB_X + NB_TQ + NB_TF + NB_BP)

__global__ void __launch_bounds__(256)
k_prep(const float* __restrict__ x,    __half* __restrict__ xh,
       const float* __restrict__ Wqkv, __half* __restrict__ wqkvT,
       const float* __restrict__ Wfc,  __half* __restrict__ wfcT,
       const float* __restrict__ bqkv, float* __restrict__ biasr)
{
    int b = blockIdx.x;
    int tid = threadIdx.x;
    if (b < NB_X) {
        size_t i = ((size_t)b * 256 + tid) * 8;
        float4 v0 = *reinterpret_cast<const float4*>(x + i);
        float4 v1 = *reinterpret_cast<const float4*>(x + i + 4);
        __half2 h[4];
        h[0] = __floats2half2_rn(v0.x, v0.y);
        h[1] = __floats2half2_rn(v0.z, v0.w);
        h[2] = __floats2half2_rn(v1.x, v1.y);
        h[3] = __floats2half2_rn(v1.z, v1.w);
        *reinterpret_cast<uint4*>(xh + i) = *reinterpret_cast<uint4*>(h);
        return;
    }
    b -= NB_X;
    if (b < NB_TQ + NB_TF) {
        const float* W; __half* out; int in_cols, perm, bx;
        if (b < NB_TQ) { W = Wqkv; out = wqkvT; in_cols = NQKV; perm = 1; bx = b; }
        else           { W = Wfc;  out = wfcT;  in_cols = DM;   perm = 0; bx = b - NB_TQ; }
        const int nbx = in_cols / 32;
        const int o0 = (bx % nbx) * 32, i0 = (bx / nbx) * 32;
        const int tx = tid & 31, ty = tid >> 5;
        __shared__ float t[32][33];
        int o = o0 + tx;
        int c = perm ? ((o & 2047) * 3 + (o >> 11)) : o;
        #pragma unroll
        for (int r = 0; r < 32; r += 8)
            t[ty + r][tx] = W[(size_t)(i0 + ty + r) * in_cols + c];
        __syncthreads();
        #pragma unroll
        for (int r = 0; r < 32; r += 8)
            out[(size_t)(o0 + ty + r) * DM + (i0 + tx)] = __float2half_rn(t[tx][ty + r]);
        return;
    }
    b -= NB_TQ + NB_TF;
    int o = b * 256 + tid;
    if (o < NQKV) biasr[o] = bqkv[(o & 2047) * 3 + (o >> 11)];
}

// ---------------- GEMM: C[bz] = alpha * A[bz] @ B[bz]^T (+bias) ----------------
// XOR swizzle: byte(row, chunk16) = row*128 + ((chunk*16) ^ ((row&7)<<4)).
// Inner loop: fragments double-buffered across ks so LDSM(ks+1) issues before
// the 32 MMAs of ks.
__global__ void __launch_bounds__(NTHREADS, 2)
k_gemm(const __half* __restrict__ A, long long lda, long long sA,
       const __half* __restrict__ B, long long ldb, long long sB,
       void* __restrict__ Cv, long long ldc, long long sC, int out_half,
       float alpha, const float* __restrict__ bias)
{
    extern __shared__ char smc[];
    const uint32_t smA0 = smem_u32(smc);
    const uint32_t smB0 = smA0 + STAGES * STG_BYTES;

    const int tid  = threadIdx.x;
    const int wid  = tid >> 5;
    const int lane = tid & 31;
    const int wm   = wid & 1;          // 0..1 (64-row slice)
    const int wn   = wid >> 1;         // 0..1 (64-col slice)
    const int tm   = blockIdx.x, tn = blockIdx.y, bz = blockIdx.z;

    // ---- cp.async addressing: 128 threads -> 16 rows/pass, 8 passes/matrix ----
    const int row0 = tid >> 3;         // 0..15
    const int cc   = tid & 7;
    const __half* gA = A + (long long)bz * sA + (long long)(tm * BM + row0) * lda + cc * 8;
    const __half* gB = B + (long long)bz * sB + (long long)(tn * BN + row0) * ldb + cc * 8;
    const uint32_t so = (uint32_t)(row0 * 128 + ((cc * 16) ^ ((row0 & 7) << 4)));

    #pragma unroll
    for (int kt = 0; kt < STAGES - 1; kt++) {
        #pragma unroll
        for (int i = 0; i < 8; i++) {
            cp16(smA0 + kt * STG_BYTES + so + i * 2048, gA + (long long)(i * 16) * lda + kt * BK);
            cp16(smB0 + kt * STG_BYTES + so + i * 2048, gB + (long long)(i * 16) * ldb + kt * BK);
        }
        asm volatile("cp.async.commit_group;\n");
    }

    float acc[4][8][4];
    #pragma unroll
    for (int mi = 0; mi < 4; mi++)
        #pragma unroll
        for (int ni = 0; ni < 8; ni++)
            #pragma unroll
            for (int j = 0; j < 4; j++) acc[mi][ni][j] = 0.0f;

    // ---- ldmatrix lane addressing ----
    const int l7 = lane & 7;
    const int rowA = wm * 64 + l7 + ((lane >> 3) & 1) * 8;
    const uint32_t uA = (uint32_t)((((lane >> 4) & 1) * 16) ^ (l7 << 4));
    // B x4 paired-ni: lanes 0-15 -> ni_{2j} rows (klo/khi by bit3), 16-31 -> ni_{2j+1} (+8)
    const int rowB = wn * 64 + ((lane >> 4) & 1) * 8 + l7;
    const uint32_t uB = (uint32_t)((((lane >> 3) & 1) * 16) ^ (l7 << 4));
    const uint32_t baseA = smA0 + (uint32_t)rowA * 128;
    const uint32_t baseB = smB0 + (uint32_t)rowB * 128;

    uint32_t af[2][4][4], bf[2][8][2];
    int s_cur = 0, s_nxt = STAGES - 1;

    #pragma unroll 1
    for (int kt = 0; kt < NK; kt++) {
        asm volatile("cp.async.wait_group 1;\n");
        __syncthreads();

        const int kl = kt + STAGES - 1;
        if (kl < NK) {
            #pragma unroll
            for (int i = 0; i < 8; i++) {
                cp16(smA0 + s_nxt * STG_BYTES + so + i * 2048, gA + (long long)(i * 16) * lda + kl * BK);
                cp16(smB0 + s_nxt * STG_BYTES + so + i * 2048, gB + (long long)(i * 16) * ldb + kl * BK);
            }
            asm volatile("cp.async.commit_group;\n");
        } else {
            asm volatile("cp.async.commit_group;\n");
        }

        const uint32_t sAc = baseA + (uint32_t)(s_cur * STG_BYTES);
        const uint32_t sBc = baseB + (uint32_t)(s_cur * STG_BYTES);

        // preload ks=0 fragments into buffer 0
        {
            const uint32_t ak = sAc + (0u ^ uA);
            const uint32_t bk = sBc + (0u ^ uB);
            #pragma unroll
            for (int mi = 0; mi < 4; mi++) ldsm_x4(af[0][mi], ak + mi * 2048);
            #pragma unroll
            for (int j = 0; j < 4; j++)    ldsm_x4(&bf[0][2 * j][0], bk + j * 2048);
        }
        #pragma unroll
        for (int ks = 0; ks < 4; ks++) {
            const int cur = ks & 1, nxt = cur ^ 1;
            if (ks < 3) {   // issue LDSM for ks+1 BEFORE the MMAs of ks
                const uint32_t ak = sAc + (((uint32_t)(ks + 1) * 32) ^ uA);
                const uint32_t bk = sBc + (((uint32_t)(ks + 1) * 32) ^ uB);
                #pragma unroll
                for (int mi = 0; mi < 4; mi++) ldsm_x4(af[nxt][mi], ak + mi * 2048);
                #pragma unroll
                for (int j = 0; j < 4; j++)    ldsm_x4(&bf[nxt][2 * j][0], bk + j * 2048);
            }
            #pragma unroll
            for (int mi = 0; mi < 4; mi++)
                #pragma unroll
                for (int ni = 0; ni < 8; ni++)
                    mma_f16_16816(acc[mi][ni], af[cur][mi], bf[cur][ni]);
        }

        s_cur = (s_cur == STAGES - 1) ? 0 : s_cur + 1;
        s_nxt = (s_nxt == STAGES - 1) ? 0 : s_nxt + 1;
    }

    // ---------------- epilogue ----------------
    const int r  = lane >> 2;
    const int cq = lane & 3;
    #pragma unroll
    for (int mi = 0; mi < 4; mi++) {
        const long long r0 = (long long)tm * BM + wm * 64 + mi * 16 + r;
        #pragma unroll
        for (int ni = 0; ni < 8; ni++) {
            const int c0 = tn * BN + wn * 64 + ni * 8 + cq * 2;
            float b0 = 0.f, b1 = 0.f;
            if (bias) { b0 = __ldg(bias + c0); b1 = __ldg(bias + c0 + 1); }
            float v00 = acc[mi][ni][0] * alpha + b0;
            float v01 = acc[mi][ni][1] * alpha + b1;
            float v10 = acc[mi][ni][2] * alpha + b0;
            float v11 = acc[mi][ni][3] * alpha + b1;
            if (out_half) {
                __half* Ch = (__half*)Cv + (long long)bz * sC;
                *reinterpret_cast<__half2*>(Ch + r0 * ldc + c0)       = __floats2half2_rn(v00, v01);
                *reinterpret_cast<__half2*>(Ch + (r0 + 8) * ldc + c0) = __floats2half2_rn(v10, v11);
            } else {
                float* Cf = (float*)Cv + (long long)bz * sC;
                *reinterpret_cast<float2*>(Cf + r0 * ldc + c0)       = make_float2(v00, v01);
                *reinterpret_cast<float2*>(Cf + (r0 + 8) * ldc + c0) = make_float2(v10, v11);
            }
        }
    }
}

// ---------------- host ----------------
extern "C" void kernel_launch(void* const* d_in, const int* in_sizes, int n_in,
                              void* d_out, int out_size)
{
    const float* x    = (const float*)d_in[0];
    const float* Wqkv = (const float*)d_in[1];
    const float* bqkv = (const float*)d_in[2];
    const float* Wfc  = (const float*)d_in[3];
    const float* bfc  = (const float*)d_in[4];
    float* out = (float*)d_out;

    void *xh, *wqkvT, *wfcT, *biasr, *qkv, *scores, *attn;
    cudaGetSymbolAddress(&xh,     g_xh);
    cudaGetSymbolAddress(&wqkvT,  g_wqkvT);
    cudaGetSymbolAddress(&wfcT,   g_wfcT);
    cudaGetSymbolAddress(&biasr,  g_biasr);
    cudaGetSymbolAddress(&qkv,    g_qkv);
    cudaGetSymbolAddress(&scores, g_scores);
    cudaGetSymbolAddress(&attn,   g_attn);

    cudaFuncSetAttribute(k_gemm, cudaFuncAttributeMaxDynamicSharedMemorySize, SMEM_DYN);

    k_prep<<<NB_PREP, 256>>>(x, (__half*)xh, Wqkv, (__half*)wqkvT,
                             Wfc, (__half*)wfcT, bqkv, (float*)biasr);

    const float scale = 0.022097086912079608f;   // 2048^-0.5

    // GEMM 1: qkv = x_h @ wqkvT^T + bias_r  -> fp16
    k_gemm<<<dim3(MTOT/BM, NQKV/BN, 1), NTHREADS, SMEM_DYN>>>(
        (const __half*)xh, DM, 0, (const __half*)wqkvT, DM, 0,
        qkv, NQKV, 0, 1, 1.0f, (const float*)biasr);

    // GEMM 2: scores[b] = Q_b @ K_b^T * scale  -> fp16
    k_gemm<<<dim3(SEQ/BM, SEQ/BN, BATCHN), NTHREADS, SMEM_DYN>>>(
        (const __half*)qkv,            NQKV, (long long)SEQ * NQKV,
        (const __half*)qkv + DM,       NQKV, (long long)SEQ * NQKV,
        scores, SEQ, (long long)SEQ * SEQ, 1, scale, nullptr);

    // GEMM 3: attn[b] = scores_b @ V_b^T  -> fp16
    k_gemm<<<dim3(SEQ/BM, SEQ/BN, BATCHN), NTHREADS, SMEM_DYN>>>(
        (const __half*)scores,         SEQ,  (long long)SEQ * SEQ,
        (const __half*)qkv + 2 * DM,   NQKV, (long long)SEQ * NQKV,
        attn, SEQ, (long long)SEQ * SEQ, 1, 1.0f, nullptr);

    // GEMM 4: out = attn @ wfcT^T + b_fc  -> fp32 (final)
    k_gemm<<<dim3(MTOT/BM, DM/BN, 1), NTHREADS, SMEM_DYN>>>(
        (const __half*)attn, SEQ, 0, (const __half*)wfcT, DM, 0,
        out, DM, 0, 0, 1.0f, bfc);
}